// round 14
// baseline (speedup 1.0000x reference)
#include <cuda_runtime.h>
#include <cuda_fp16.h>
#include <math_constants.h>
#include <cstdint>

#define C_DIM 128
#define D_DEG 64
#define NODE_NUM 8192
#define N_TOTAL 200000
#define NEG_SLOPE 0.2f
#define GRID_CTAS 740        // 5 CTAs per SM target
#define GROUPS 2             // independent 128-thread groups per 256-thread CTA
#define GSTREAMS (GRID_CTAS * GROUPS)   // 1480 node streams

// smem layout (dynamic), per-CTA (2 groups)
#define OFF_STAGE 0                 // [2][64][128] fp16 = 32KB (warp-private rows)
#define OFF_PARTA 32768             // [2][4][32] uint2 fp16 colmax partials = 2KB
#define OFF_PARTP 34816             // [2][4][128] f32 pool partials = 4KB
#define OFF_SRAW  38912             // [2][64] f32 = 512B
#define OFF_SARR  39424             // [2][64] f32 = 512B
#define OFF_WRED  39936             // [2][4] f32
#define SMEM_BYTES 39968

// Fused fp16 table: S[n][c] = fp16(feat[n][c] + mem[n][c]); 51.2MB static scratch.
__device__ __half2 g_S[(size_t)N_TOTAL * (C_DIM / 2)];
// Folded weights: v = W_max @ W_score[:128]; c0 = dot(b_max, W_score[:128]) + b_score
__device__ float g_v[C_DIM];
__device__ float g_c0;

// ---- Kernel 1 (R12-proven): streaming fuse, one uint4 store per thread ----
__global__ __launch_bounds__(512)
void fuse_kernel(const float4* __restrict__ feat4,
                 const float4* __restrict__ mem4,
                 const float* __restrict__ Wmax,
                 const float* __restrict__ bmax,
                 const float* __restrict__ Wscore,
                 const float* __restrict__ bscore) {
    if (blockIdx.x == 0) {
        __shared__ float ws1[C_DIM];
        int t = threadIdx.x;
        if (t < C_DIM) ws1[t] = Wscore[t];
        __syncthreads();
        if (t < C_DIM) {
            const float* row = Wmax + t * C_DIM;
            float acc = 0.f;
#pragma unroll 8
            for (int k = 0; k < C_DIM; k++) acc += row[k] * ws1[k];
            g_v[t] = acc;
            if (t == 0) {
                float c0 = bscore[0];
                for (int k = 0; k < C_DIM; k++) c0 += bmax[k] * ws1[k];
                g_c0 = c0;
            }
        }
    }
    // exactly one uint4 store per thread: grid 6250 x 512 == 3.2M
    const int i = blockIdx.x * blockDim.x + threadIdx.x;
    // streaming (evict-first) reads keep the S output resident in L2
    float4 a0 = __ldcs(feat4 + 2 * i);
    float4 b0 = __ldcs(mem4 + 2 * i);
    float4 a1 = __ldcs(feat4 + 2 * i + 1);
    float4 b1 = __ldcs(mem4 + 2 * i + 1);
    __half2 h0 = __floats2half2_rn(a0.x + b0.x, a0.y + b0.y);
    __half2 h1 = __floats2half2_rn(a0.z + b0.z, a0.w + b0.w);
    __half2 h2 = __floats2half2_rn(a1.x + b1.x, a1.y + b1.y);
    __half2 h3 = __floats2half2_rn(a1.z + b1.z, a1.w + b1.w);
    uint4 pack;
    pack.x = *reinterpret_cast<unsigned int*>(&h0);
    pack.y = *reinterpret_cast<unsigned int*>(&h1);
    pack.z = *reinterpret_cast<unsigned int*>(&h2);
    pack.w = *reinterpret_cast<unsigned int*>(&h3);
    reinterpret_cast<uint4*>(g_S)[i] = pack;
}

__device__ __forceinline__ void cp16(unsigned int dst, const void* src) {
    asm volatile("cp.async.cg.shared.global [%0], [%1], 16;\n"
                 :: "r"(dst), "l"(src) : "memory");
}
__device__ __forceinline__ void gbar(int id) {
    asm volatile("bar.sync %0, 128;" :: "r"(id) : "memory");
}
__device__ __forceinline__ __half2 u2h(unsigned int u) {
    return *reinterpret_cast<__half2*>(&u);
}

// ---- Kernel 2: R11-proven pipeline reshaped to 256-thread CTAs, 5 CTAs/SM ----
__global__ __launch_bounds__(256, 5)
void community_kernel(const float* __restrict__ Wscore,
                      const float* __restrict__ Wfit,
                      const float* __restrict__ bfit,
                      float* __restrict__ out_cluster,   // [NODE_NUM, C]
                      float* __restrict__ out_scores,    // [NODE_NUM, D]
                      float* __restrict__ out_fit,       // [NODE_NUM]
                      const int* __restrict__ neighbors)
{
    extern __shared__ char smem[];

    const int t    = threadIdx.x;
    const int lane = t & 31;
    const int wid  = t >> 5;     // 0..7
    const int g    = wid >> 2;   // group 0..1
    const int gw   = wid & 3;    // warp within group
    const int tg   = t & 127;    // thread within group
    const int barid = g + 1;

    char*  stg_b = smem + OFF_STAGE + g * 16384;                // group stage, bytes
    __half2* stg = (__half2*)stg_b;                             // [64][64] half2
    uint2* partA = (uint2*)(smem + OFF_PARTA) + g * 128;        // [4][32] fp16 colmax
    float* partP = (float*)(smem + OFF_PARTP) + g * 512;        // pool partials
    float* srawg = (float*)(smem + OFF_SRAW) + g * 64;
    float* sarrg = (float*)(smem + OFF_SARR) + g * 64;
    float* wredg = (float*)(smem + OFF_WRED) + g * 4;
    const unsigned int stg_u = (unsigned int)__cvta_generic_to_shared(stg_b);
    const char* Sbase = (const char*)g_S;

    // loop-invariant weights (gv4 intentionally NOT kept live: loaded in softmax)
    const float4 w2v   = *reinterpret_cast<const float4*>(Wscore + C_DIM + 4 * lane);
    const float  wfitv = Wfit[tg];
    const float  bfitv = bfit[0];
    const float  c0    = g_c0;
    const __half2 NEGINF2 = __halves2half2(__ushort_as_half(0xFC00u),
                                           __ushort_as_half(0xFC00u));

    int node = blockIdx.x * GROUPS + g;
    if (node >= NODE_NUM) return;   // (GSTREAMS <= NODE_NUM, never taken; safety)
    int prev = -1;

    // ---- prologue: warp stages its OWN 16 rows (ids: 1 LDG + shfl) ----
    {
        int myid = 0;
        if (lane < 16) myid = neighbors[node * D_DEG + gw * 16 + lane];
#pragma unroll
        for (int i = 0; i < 8; i++) {
            int c  = lane + 32 * i;          // chunk within warp's 16 rows
            int r  = c >> 4, ch = c & 15;
            long long nid = __shfl_sync(0xffffffffu, myid, r);
            int row = gw * 16 + r;
            cp16(stg_u + (unsigned)(row * 256 + ch * 16), Sbase + nid * 256 + ch * 16);
        }
        asm volatile("cp.async.commit_group;\n" ::: "memory");
    }

    while (true) {
        const int  next     = node + GSTREAMS;
        const bool has_next = (next < NODE_NUM);

        asm volatile("cp.async.wait_group 0;\n" ::: "memory");
        // stage is warp-private: no barrier needed before reading it.

        // ---- Phase A: quad row-dot reduction + fp16 colmax over own 16 rows ----
        __half2 cmx0 = NEGINF2, cmx1 = NEGINF2;
#pragma unroll
        for (int k = 0; k < 4; k++) {
            int r0 = gw * 16 + 4 * k;
            uint2 u0 = *reinterpret_cast<const uint2*>(stg + (r0 + 0) * 64 + lane * 2);
            uint2 u1 = *reinterpret_cast<const uint2*>(stg + (r0 + 1) * 64 + lane * 2);
            uint2 u2 = *reinterpret_cast<const uint2*>(stg + (r0 + 2) * 64 + lane * 2);
            uint2 u3 = *reinterpret_cast<const uint2*>(stg + (r0 + 3) * 64 + lane * 2);
            __half2 a0x = u2h(u0.x), a0y = u2h(u0.y);
            __half2 a1x = u2h(u1.x), a1y = u2h(u1.y);
            __half2 a2x = u2h(u2.x), a2y = u2h(u2.y);
            __half2 a3x = u2h(u3.x), a3y = u2h(u3.y);
            cmx0 = __hmax2(cmx0, __hmax2(__hmax2(a0x, a1x), __hmax2(a2x, a3x)));
            cmx1 = __hmax2(cmx1, __hmax2(__hmax2(a0y, a1y), __hmax2(a2y, a3y)));
            float2 f0x = __half22float2(a0x), f0y = __half22float2(a0y);
            float2 f1x = __half22float2(a1x), f1y = __half22float2(a1y);
            float2 f2x = __half22float2(a2x), f2y = __half22float2(a2y);
            float2 f3x = __half22float2(a3x), f3y = __half22float2(a3y);
            float p0 = f0x.x * w2v.x + f0x.y * w2v.y + f0y.x * w2v.z + f0y.y * w2v.w;
            float p1 = f1x.x * w2v.x + f1x.y * w2v.y + f1y.x * w2v.z + f1y.y * w2v.w;
            float p2 = f2x.x * w2v.x + f2x.y * w2v.y + f2y.x * w2v.z + f2y.y * w2v.w;
            float p3 = f3x.x * w2v.x + f3x.y * w2v.y + f3y.x * w2v.z + f3y.y * w2v.w;
            // quad butterfly: lane%4 == m ends with row r0+m's full dot
            float tA = (lane & 1) ? p0 : p1;
            tA = __shfl_xor_sync(0xffffffffu, tA, 1);
            float v01 = ((lane & 1) ? p1 : p0) + tA;
            float tB = (lane & 1) ? p2 : p3;
            tB = __shfl_xor_sync(0xffffffffu, tB, 1);
            float v23 = ((lane & 1) ? p3 : p2) + tB;
            float tC = (lane & 2) ? v01 : v23;
            tC = __shfl_xor_sync(0xffffffffu, tC, 2);
            float v = ((lane & 2) ? v23 : v01) + tC;
            v += __shfl_xor_sync(0xffffffffu, v, 4);
            v += __shfl_xor_sync(0xffffffffu, v, 8);
            v += __shfl_xor_sync(0xffffffffu, v, 16);
            if (lane < 4) srawg[r0 + lane] = v;
        }
        partA[gw * 32 + lane] = make_uint2(*reinterpret_cast<unsigned int*>(&cmx0),
                                           *reinterpret_cast<unsigned int*>(&cmx1));
        gbar(barid);   // B2: partA + sraw visible (also orders prev iter's wred writes)

        // ---- deferred fitness for previous node (ordered by B2) ----
        if (prev >= 0 && tg == 0) {
            float s = wredg[0] + wredg[1] + wredg[2] + wredg[3] + bfitv;
            out_fit[prev] = 1.f / (1.f + __expf(-s));
        }

        // ---- warp 0 only: colmax combine -> s_const -> softmax -> sarr ----
        if (gw == 0) {
            uint2 m0 = partA[0   + lane], m1 = partA[32  + lane];
            uint2 m2 = partA[64  + lane], m3 = partA[96  + lane];
            __half2 x0 = __hmax2(__hmax2(u2h(m0.x), u2h(m1.x)),
                                 __hmax2(u2h(m2.x), u2h(m3.x)));
            __half2 x1 = __hmax2(__hmax2(u2h(m0.y), u2h(m1.y)),
                                 __hmax2(u2h(m2.y), u2h(m3.y)));
            float2 c01 = __half22float2(x0);
            float2 c23 = __half22float2(x1);
            const float4 gv4 = __ldg(reinterpret_cast<const float4*>(g_v + 4 * lane));
            float p = c01.x * gv4.x + c01.y * gv4.y + c23.x * gv4.z + c23.y * gv4.w;
#pragma unroll
            for (int o = 16; o > 0; o >>= 1) p += __shfl_xor_sync(0xffffffffu, p, o);
            const float s_const = p + c0;

            float a0 = s_const + srawg[lane];
            float a1 = s_const + srawg[lane + 32];
            a0 = (a0 >= 0.f) ? a0 : NEG_SLOPE * a0;
            a1 = (a1 >= 0.f) ? a1 : NEG_SLOPE * a1;
            float mx = fmaxf(a0, a1);
#pragma unroll
            for (int o = 16; o > 0; o >>= 1) mx = fmaxf(mx, __shfl_xor_sync(0xffffffffu, mx, o));
            float e0 = __expf(a0 - mx), e1 = __expf(a1 - mx);
            float sm = e0 + e1;
#pragma unroll
            for (int o = 16; o > 0; o >>= 1) sm += __shfl_xor_sync(0xffffffffu, sm, o);
            float inv = 1.f / sm;
            float s0 = e0 * inv, s1 = e1 * inv;
            sarrg[lane]      = s0;
            sarrg[lane + 32] = s1;
            out_scores[node * D_DEG + lane]      = s0;
            out_scores[node * D_DEG + lane + 32] = s1;
        }
        gbar(barid);   // B3: sarr ready

        // ---- next-node ids (loaded early, consumed in D's interleaved prefetch) ----
        int myid2 = 0;
        if (has_next && lane < 16) myid2 = neighbors[next * D_DEG + gw * 16 + lane];

        // ---- Phase D: weighted pooling; prefetch interleaved every 2 rows ----
        {
            float a0 = 0.f, a1 = 0.f, a2 = 0.f, a3 = 0.f;
#pragma unroll
            for (int r = 0; r < 16; r++) {
                int row = gw * 16 + r;
                float sc = sarrg[row];   // LDS broadcast
                uint2 u = *reinterpret_cast<const uint2*>(stg + row * 64 + lane * 2);
                float2 f0 = __half22float2(u2h(u.x));
                float2 f1 = __half22float2(u2h(u.y));
                a0 = fmaf(sc, f0.x, a0); a1 = fmaf(sc, f0.y, a1);
                a2 = fmaf(sc, f1.x, a2); a3 = fmaf(sc, f1.y, a3);
                // after the odd row of each pair is consumed, refill that pair
                if ((r & 1) && has_next) {
                    int pair = r >> 1;                  // 0..7
                    int c  = pair * 32 + lane;          // chunk id 0..255
                    int rr = c >> 4, ch = c & 15;       // rr in {2*pair, 2*pair+1} <= r
                    long long nid = __shfl_sync(0xffffffffu, myid2, rr);
                    int wrow = gw * 16 + rr;
                    cp16(stg_u + (unsigned)(wrow * 256 + ch * 16),
                         Sbase + nid * 256 + ch * 16);
                }
            }
            if (has_next) asm volatile("cp.async.commit_group;\n" ::: "memory");
            *reinterpret_cast<float4*>(partP + gw * 128 + lane * 4) = make_float4(a0, a1, a2, a3);
        }
        gbar(barid);   // B4: partP visible

        // ---- Phase E: cluster sum + output + fitness partials ----
        {
            float cf = partP[tg] + partP[128 + tg] + partP[256 + tg] + partP[384 + tg];
            out_cluster[node * C_DIM + tg] = cf;
            float p = cf * wfitv;
#pragma unroll
            for (int o = 16; o > 0; o >>= 1) p += __shfl_xor_sync(0xffffffffu, p, o);
            if (lane == 0) wredg[gw] = p;   // consumed after next iter's B2 (or tail)
        }

        prev = node;
        if (!has_next) break;
        node = next;
    }

    // ---- tail: final node's fitness ----
    gbar(barid);
    if (tg == 0) {
        float s = wredg[0] + wredg[1] + wredg[2] + wredg[3] + bfitv;
        out_fit[prev] = 1.f / (1.f + __expf(-s));
    }
}

extern "C" void kernel_launch(void* const* d_in, const int* in_sizes, int n_in,
                              void* d_out, int out_size) {
    const float* feat   = (const float*)d_in[0];
    const float* mem    = (const float*)d_in[1];
    const float* Wmax   = (const float*)d_in[2];
    const float* bmax   = (const float*)d_in[3];
    const float* Wscore = (const float*)d_in[4];
    const float* bscore = (const float*)d_in[5];
    const float* Wfit   = (const float*)d_in[6];
    const float* bfit   = (const float*)d_in[7];
    const int*   nbrs   = (const int*)d_in[8];

    float* out = (float*)d_out;
    float* out_cluster = out;                                        // 8192*128
    float* out_scores  = out + NODE_NUM * C_DIM;                     // 8192*64
    float* out_fit     = out + NODE_NUM * C_DIM + NODE_NUM * D_DEG;  // 8192

    cudaFuncSetAttribute(community_kernel,
                         cudaFuncAttributeMaxDynamicSharedMemorySize, SMEM_BYTES);

    // 6250 x 512 threads == 3.2M == exactly one 16B S-store per thread
    fuse_kernel<<<6250, 512>>>((const float4*)feat, (const float4*)mem,
                               Wmax, bmax, Wscore, bscore);
    community_kernel<<<GRID_CTAS, 256, SMEM_BYTES>>>(Wscore, Wfit, bfit,
                                                     out_cluster, out_scores, out_fit, nbrs);
}

// round 15
// speedup vs baseline: 1.0972x; 1.0972x over previous
#include <cuda_runtime.h>
#include <cuda_fp16.h>
#include <math_constants.h>
#include <cstdint>

#define C_DIM 128
#define D_DEG 64
#define NODE_NUM 8192
#define N_TOTAL 200000
#define NEG_SLOPE 0.2f
#define GRID_CTAS 296        // 2 persistent CTAs per SM
#define GROUPS 4             // independent 128-thread groups per CTA
#define GSTREAMS (GRID_CTAS * GROUPS)   // 1184 node streams

// smem layout (dynamic)
#define OFF_STAGE 0                 // [4][64][128] fp16 = 64KB (warp-private rows)
#define OFF_PARTA 65536             // [4][4][32] uint2 fp16 colmax partials = 4KB
#define OFF_PARTP 69632             // [4][4][128] f32 pool partials = 8KB
#define OFF_SRAW  77824             // [4][64] f32 = 1KB
#define OFF_SARR  78848             // [4][64] f32 = 1KB
#define OFF_WRED  79872             // [4][4] f32
#define SMEM_BYTES 79936

// Fused fp16 table: S[n][c] = fp16(feat[n][c] + mem[n][c]); 51.2MB static scratch.
__device__ __half2 g_S[(size_t)N_TOTAL * (C_DIM / 2)];
// Folded weights: v = W_max @ W_score[:128]; c0 = dot(b_max, W_score[:128]) + b_score
__device__ float g_v[C_DIM];
__device__ float g_c0;

// ---- Kernel 1 (R12-proven): streaming fuse, one uint4 store per thread ----
__global__ __launch_bounds__(512)
void fuse_kernel(const float4* __restrict__ feat4,
                 const float4* __restrict__ mem4,
                 const float* __restrict__ Wmax,
                 const float* __restrict__ bmax,
                 const float* __restrict__ Wscore,
                 const float* __restrict__ bscore) {
    if (blockIdx.x == 0) {
        __shared__ float ws1[C_DIM];
        int t = threadIdx.x;
        if (t < C_DIM) ws1[t] = Wscore[t];
        __syncthreads();
        if (t < C_DIM) {
            const float* row = Wmax + t * C_DIM;
            float acc = 0.f;
#pragma unroll 8
            for (int k = 0; k < C_DIM; k++) acc += row[k] * ws1[k];
            g_v[t] = acc;
            if (t == 0) {
                float c0 = bscore[0];
                for (int k = 0; k < C_DIM; k++) c0 += bmax[k] * ws1[k];
                g_c0 = c0;
            }
        }
    }
    // exactly one uint4 store per thread: grid 6250 x 512 == 3.2M
    const int i = blockIdx.x * blockDim.x + threadIdx.x;
    // streaming (evict-first) reads keep the S output resident in L2
    float4 a0 = __ldcs(feat4 + 2 * i);
    float4 b0 = __ldcs(mem4 + 2 * i);
    float4 a1 = __ldcs(feat4 + 2 * i + 1);
    float4 b1 = __ldcs(mem4 + 2 * i + 1);
    __half2 h0 = __floats2half2_rn(a0.x + b0.x, a0.y + b0.y);
    __half2 h1 = __floats2half2_rn(a0.z + b0.z, a0.w + b0.w);
    __half2 h2 = __floats2half2_rn(a1.x + b1.x, a1.y + b1.y);
    __half2 h3 = __floats2half2_rn(a1.z + b1.z, a1.w + b1.w);
    uint4 pack;
    pack.x = *reinterpret_cast<unsigned int*>(&h0);
    pack.y = *reinterpret_cast<unsigned int*>(&h1);
    pack.z = *reinterpret_cast<unsigned int*>(&h2);
    pack.w = *reinterpret_cast<unsigned int*>(&h3);
    reinterpret_cast<uint4*>(g_S)[i] = pack;
}

__device__ __forceinline__ void cp16(unsigned int dst, const void* src) {
    asm volatile("cp.async.cg.shared.global [%0], [%1], 16;\n"
                 :: "r"(dst), "l"(src) : "memory");
}
__device__ __forceinline__ void cp_commit() {
    asm volatile("cp.async.commit_group;\n" ::: "memory");
}
__device__ __forceinline__ void gbar(int id) {
    asm volatile("bar.sync %0, 128;" :: "r"(id) : "memory");
}
__device__ __forceinline__ __half2 u2h(unsigned int u) {
    return *reinterpret_cast<__half2*>(&u);
}

// ---- Kernel 2 (R13 base + split commit groups for latency hiding) ----
__global__ __launch_bounds__(512, 2)
void community_kernel(const float* __restrict__ Wscore,
                      const float* __restrict__ Wfit,
                      const float* __restrict__ bfit,
                      float* __restrict__ out_cluster,   // [NODE_NUM, C]
                      float* __restrict__ out_scores,    // [NODE_NUM, D]
                      float* __restrict__ out_fit,       // [NODE_NUM]
                      const int* __restrict__ neighbors)
{
    extern __shared__ char smem[];

    const int t    = threadIdx.x;
    const int lane = t & 31;
    const int wid  = t >> 5;     // 0..15
    const int g    = wid >> 2;   // group 0..3
    const int gw   = wid & 3;    // warp within group
    const int tg   = t & 127;    // thread within group
    const int barid = g + 1;

    char*  stg_b = smem + OFF_STAGE + g * 16384;                // group stage, bytes
    __half2* stg = (__half2*)stg_b;                             // [64][64] half2
    uint2* partA = (uint2*)(smem + OFF_PARTA) + g * 128;        // [4][32] fp16 colmax
    float* partP = (float*)(smem + OFF_PARTP) + g * 512;        // pool partials
    float* srawg = (float*)(smem + OFF_SRAW) + g * 64;
    float* sarrg = (float*)(smem + OFF_SARR) + g * 64;
    float* wredg = (float*)(smem + OFF_WRED) + g * 4;
    const unsigned int stg_u = (unsigned int)__cvta_generic_to_shared(stg_b);
    const char* Sbase = (const char*)g_S;

    // loop-invariant weights
    const float4 w2v   = *reinterpret_cast<const float4*>(Wscore + C_DIM + 4 * lane);
    const float4 gv4   = *reinterpret_cast<const float4*>(g_v + 4 * lane);
    const float  wfitv = Wfit[tg];
    const float  bfitv = bfit[0];
    const float  c0    = g_c0;
    const __half2 NEGINF2 = __halves2half2(__ushort_as_half(0xFC00u),
                                           __ushort_as_half(0xFC00u));

    int node = blockIdx.x * GROUPS + g;
    int prev = -1;

    // ---- prologue: stage first node's rows in TWO commit groups ----
    {
        int myid = 0;
        if (lane < 16) myid = neighbors[node * D_DEG + gw * 16 + lane];
#pragma unroll
        for (int i = 0; i < 4; i++) {         // chunks for rows 0..7 of block
            int c  = lane + 32 * i;
            int r  = c >> 4, ch = c & 15;
            long long nid = __shfl_sync(0xffffffffu, myid, r);
            int row = gw * 16 + r;
            cp16(stg_u + (unsigned)(row * 256 + ch * 16), Sbase + nid * 256 + ch * 16);
        }
        cp_commit();                           // G1: rows 0..7
#pragma unroll
        for (int i = 4; i < 8; i++) {         // chunks for rows 8..15
            int c  = lane + 32 * i;
            int r  = c >> 4, ch = c & 15;
            long long nid = __shfl_sync(0xffffffffu, myid, r);
            int row = gw * 16 + r;
            cp16(stg_u + (unsigned)(row * 256 + ch * 16), Sbase + nid * 256 + ch * 16);
        }
        cp_commit();                           // G2: rows 8..15
    }

    while (true) {
        const int  next     = node + GSTREAMS;
        const bool has_next = (next < NODE_NUM);

        // ---- next-node ids loaded at loop top (idle LSU slot) ----
        int myid2 = 0;
        if (has_next && lane < 16) myid2 = neighbors[next * D_DEG + gw * 16 + lane];

        asm volatile("cp.async.wait_group 1;\n" ::: "memory");   // G1: rows 0..7 ready

        // ---- Phase A: quad row-dot reduction + fp16 colmax; split halves ----
        __half2 cmx0 = NEGINF2, cmx1 = NEGINF2;
#pragma unroll
        for (int k = 0; k < 4; k++) {
            if (k == 2)
                asm volatile("cp.async.wait_group 0;\n" ::: "memory");  // G2: rows 8..15
            int r0 = gw * 16 + 4 * k;
            uint2 u0 = *reinterpret_cast<const uint2*>(stg + (r0 + 0) * 64 + lane * 2);
            uint2 u1 = *reinterpret_cast<const uint2*>(stg + (r0 + 1) * 64 + lane * 2);
            uint2 u2 = *reinterpret_cast<const uint2*>(stg + (r0 + 2) * 64 + lane * 2);
            uint2 u3 = *reinterpret_cast<const uint2*>(stg + (r0 + 3) * 64 + lane * 2);
            __half2 a0x = u2h(u0.x), a0y = u2h(u0.y);
            __half2 a1x = u2h(u1.x), a1y = u2h(u1.y);
            __half2 a2x = u2h(u2.x), a2y = u2h(u2.y);
            __half2 a3x = u2h(u3.x), a3y = u2h(u3.y);
            cmx0 = __hmax2(cmx0, __hmax2(__hmax2(a0x, a1x), __hmax2(a2x, a3x)));
            cmx1 = __hmax2(cmx1, __hmax2(__hmax2(a0y, a1y), __hmax2(a2y, a3y)));
            float2 f0x = __half22float2(a0x), f0y = __half22float2(a0y);
            float2 f1x = __half22float2(a1x), f1y = __half22float2(a1y);
            float2 f2x = __half22float2(a2x), f2y = __half22float2(a2y);
            float2 f3x = __half22float2(a3x), f3y = __half22float2(a3y);
            float p0 = f0x.x * w2v.x + f0x.y * w2v.y + f0y.x * w2v.z + f0y.y * w2v.w;
            float p1 = f1x.x * w2v.x + f1x.y * w2v.y + f1y.x * w2v.z + f1y.y * w2v.w;
            float p2 = f2x.x * w2v.x + f2x.y * w2v.y + f2y.x * w2v.z + f2y.y * w2v.w;
            float p3 = f3x.x * w2v.x + f3x.y * w2v.y + f3y.x * w2v.z + f3y.y * w2v.w;
            // quad butterfly: lane%4 == m ends with row r0+m's full dot
            float tA = (lane & 1) ? p0 : p1;
            tA = __shfl_xor_sync(0xffffffffu, tA, 1);
            float v01 = ((lane & 1) ? p1 : p0) + tA;
            float tB = (lane & 1) ? p2 : p3;
            tB = __shfl_xor_sync(0xffffffffu, tB, 1);
            float v23 = ((lane & 1) ? p3 : p2) + tB;
            float tC = (lane & 2) ? v01 : v23;
            tC = __shfl_xor_sync(0xffffffffu, tC, 2);
            float v = ((lane & 2) ? v23 : v01) + tC;
            v += __shfl_xor_sync(0xffffffffu, v, 4);
            v += __shfl_xor_sync(0xffffffffu, v, 8);
            v += __shfl_xor_sync(0xffffffffu, v, 16);
            if (lane < 4) srawg[r0 + lane] = v;
        }
        partA[gw * 32 + lane] = make_uint2(*reinterpret_cast<unsigned int*>(&cmx0),
                                           *reinterpret_cast<unsigned int*>(&cmx1));
        gbar(barid);   // B2: partA + sraw visible (also orders prev iter's wred writes)

        // ---- deferred fitness for previous node (ordered by B2) ----
        if (prev >= 0 && tg == 0) {
            float s = wredg[0] + wredg[1] + wredg[2] + wredg[3] + bfitv;
            out_fit[prev] = 1.f / (1.f + __expf(-s));
        }

        // ---- warp 0 only: colmax combine -> s_const -> softmax -> sarr ----
        if (gw == 0) {
            uint2 m0 = partA[0   + lane], m1 = partA[32  + lane];
            uint2 m2 = partA[64  + lane], m3 = partA[96  + lane];
            __half2 x0 = __hmax2(__hmax2(u2h(m0.x), u2h(m1.x)),
                                 __hmax2(u2h(m2.x), u2h(m3.x)));
            __half2 x1 = __hmax2(__hmax2(u2h(m0.y), u2h(m1.y)),
                                 __hmax2(u2h(m2.y), u2h(m3.y)));
            float2 c01 = __half22float2(x0);
            float2 c23 = __half22float2(x1);
            float p = c01.x * gv4.x + c01.y * gv4.y + c23.x * gv4.z + c23.y * gv4.w;
#pragma unroll
            for (int o = 16; o > 0; o >>= 1) p += __shfl_xor_sync(0xffffffffu, p, o);
            const float s_const = p + c0;

            float a0 = s_const + srawg[lane];
            float a1 = s_const + srawg[lane + 32];
            a0 = (a0 >= 0.f) ? a0 : NEG_SLOPE * a0;
            a1 = (a1 >= 0.f) ? a1 : NEG_SLOPE * a1;
            float mx = fmaxf(a0, a1);
#pragma unroll
            for (int o = 16; o > 0; o >>= 1) mx = fmaxf(mx, __shfl_xor_sync(0xffffffffu, mx, o));
            float e0 = __expf(a0 - mx), e1 = __expf(a1 - mx);
            float sm = e0 + e1;
#pragma unroll
            for (int o = 16; o > 0; o >>= 1) sm += __shfl_xor_sync(0xffffffffu, sm, o);
            float inv = 1.f / sm;
            float s0 = e0 * inv, s1 = e1 * inv;
            sarrg[lane]      = s0;
            sarrg[lane + 32] = s1;
            out_scores[node * D_DEG + lane]      = s0;
            out_scores[node * D_DEG + lane + 32] = s1;
        }
        gbar(barid);   // B3: sarr ready

        // ---- Phase D: weighted pooling; prefetch interleaved, 2 commit groups ----
        {
            float a0 = 0.f, a1 = 0.f, a2 = 0.f, a3 = 0.f;
#pragma unroll
            for (int r = 0; r < 16; r++) {
                int row = gw * 16 + r;
                float sc = sarrg[row];   // LDS broadcast
                uint2 u = *reinterpret_cast<const uint2*>(stg + row * 64 + lane * 2);
                float2 f0 = __half22float2(u2h(u.x));
                float2 f1 = __half22float2(u2h(u.y));
                a0 = fmaf(sc, f0.x, a0); a1 = fmaf(sc, f0.y, a1);
                a2 = fmaf(sc, f1.x, a2); a3 = fmaf(sc, f1.y, a3);
                // after the odd row of each pair is consumed, refill that pair
                if ((r & 1) && has_next) {
                    int pair = r >> 1;                  // 0..7
                    int c  = pair * 32 + lane;          // chunk id 0..255
                    int rr = c >> 4, ch = c & 15;       // rr in {2*pair, 2*pair+1} <= r
                    long long nid = __shfl_sync(0xffffffffu, myid2, rr);
                    int wrow = gw * 16 + rr;
                    cp16(stg_u + (unsigned)(wrow * 256 + ch * 16),
                         Sbase + nid * 256 + ch * 16);
                    if (r == 7)  cp_commit();           // G1: rows 0..7
                    if (r == 15) cp_commit();           // G2: rows 8..15
                }
            }
            *reinterpret_cast<float4*>(partP + gw * 128 + lane * 4) = make_float4(a0, a1, a2, a3);
        }
        gbar(barid);   // B4: partP visible

        // ---- Phase E: cluster sum + output + fitness partials ----
        {
            float cf = partP[tg] + partP[128 + tg] + partP[256 + tg] + partP[384 + tg];
            out_cluster[node * C_DIM + tg] = cf;
            float p = cf * wfitv;
#pragma unroll
            for (int o = 16; o > 0; o >>= 1) p += __shfl_xor_sync(0xffffffffu, p, o);
            if (lane == 0) wredg[gw] = p;   // consumed after next iter's B2 (or tail)
        }

        prev = node;
        if (!has_next) break;
        node = next;
    }

    // ---- tail: final node's fitness ----
    gbar(barid);
    if (tg == 0) {
        float s = wredg[0] + wredg[1] + wredg[2] + wredg[3] + bfitv;
        out_fit[prev] = 1.f / (1.f + __expf(-s));
    }
}

extern "C" void kernel_launch(void* const* d_in, const int* in_sizes, int n_in,
                              void* d_out, int out_size) {
    const float* feat   = (const float*)d_in[0];
    const float* mem    = (const float*)d_in[1];
    const float* Wmax   = (const float*)d_in[2];
    const float* bmax   = (const float*)d_in[3];
    const float* Wscore = (const float*)d_in[4];
    const float* bscore = (const float*)d_in[5];
    const float* Wfit   = (const float*)d_in[6];
    const float* bfit   = (const float*)d_in[7];
    const int*   nbrs   = (const int*)d_in[8];

    float* out = (float*)d_out;
    float* out_cluster = out;                                        // 8192*128
    float* out_scores  = out + NODE_NUM * C_DIM;                     // 8192*64
    float* out_fit     = out + NODE_NUM * C_DIM + NODE_NUM * D_DEG;  // 8192

    cudaFuncSetAttribute(community_kernel,
                         cudaFuncAttributeMaxDynamicSharedMemorySize, SMEM_BYTES);

    // 6250 x 512 threads == 3.2M == exactly one 16B S-store per thread
    fuse_kernel<<<6250, 512>>>((const float4*)feat, (const float4*)mem,
                               Wmax, bmax, Wscore, bscore);
    community_kernel<<<GRID_CTAS, 512, SMEM_BYTES>>>(Wscore, Wfit, bfit,
                                                     out_cluster, out_scores, out_fit, nbrs);
}

// round 16
// speedup vs baseline: 1.0988x; 1.0015x over previous
#include <cuda_runtime.h>
#include <cuda_fp16.h>
#include <math_constants.h>
#include <cstdint>

#define C_DIM 128
#define D_DEG 64
#define NODE_NUM 8192
#define N_TOTAL 200000
#define NEG_SLOPE 0.2f
#define GRID_CTAS 296        // 2 persistent CTAs per SM
#define GROUPS 4             // independent 128-thread groups per CTA
#define GSTREAMS (GRID_CTAS * GROUPS)   // 1184 node streams

// smem layout (dynamic)
#define OFF_STAGE 0                 // [4][64][128] fp16 = 64KB (warp-private rows)
#define OFF_PARTA 65536             // [4][4][32] uint2 fp16 colmax partials = 4KB
#define OFF_PARTP 69632             // [4][4][128] f32 pool partials = 8KB
#define OFF_SRAW  77824             // [4][64] f32 = 1KB
#define OFF_SARR  78848             // [4][64] f32 = 1KB
#define OFF_WRED  79872             // [4][2][4] f32 parity-buffered fitness partials
#define SMEM_BYTES 80000

// Fused fp16 table: S[n][c] = fp16(feat[n][c] + mem[n][c]); 51.2MB static scratch.
__device__ __half2 g_S[(size_t)N_TOTAL * (C_DIM / 2)];
// Folded weights: v = W_max @ W_score[:128]; c0 = dot(b_max, W_score[:128]) + b_score
__device__ float g_v[C_DIM];
__device__ float g_c0;

// ---- Kernel 1 (R12-proven): streaming fuse, one uint4 store per thread ----
__global__ __launch_bounds__(512)
void fuse_kernel(const float4* __restrict__ feat4,
                 const float4* __restrict__ mem4,
                 const float* __restrict__ Wmax,
                 const float* __restrict__ bmax,
                 const float* __restrict__ Wscore,
                 const float* __restrict__ bscore) {
    if (blockIdx.x == 0) {
        __shared__ float ws1[C_DIM];
        int t = threadIdx.x;
        if (t < C_DIM) ws1[t] = Wscore[t];
        __syncthreads();
        if (t < C_DIM) {
            const float* row = Wmax + t * C_DIM;
            float acc = 0.f;
#pragma unroll 8
            for (int k = 0; k < C_DIM; k++) acc += row[k] * ws1[k];
            g_v[t] = acc;
            if (t == 0) {
                float c0 = bscore[0];
                for (int k = 0; k < C_DIM; k++) c0 += bmax[k] * ws1[k];
                g_c0 = c0;
            }
        }
    }
    // exactly one uint4 store per thread: grid 6250 x 512 == 3.2M
    const int i = blockIdx.x * blockDim.x + threadIdx.x;
    // streaming (evict-first) reads keep the S output resident in L2
    float4 a0 = __ldcs(feat4 + 2 * i);
    float4 b0 = __ldcs(mem4 + 2 * i);
    float4 a1 = __ldcs(feat4 + 2 * i + 1);
    float4 b1 = __ldcs(mem4 + 2 * i + 1);
    __half2 h0 = __floats2half2_rn(a0.x + b0.x, a0.y + b0.y);
    __half2 h1 = __floats2half2_rn(a0.z + b0.z, a0.w + b0.w);
    __half2 h2 = __floats2half2_rn(a1.x + b1.x, a1.y + b1.y);
    __half2 h3 = __floats2half2_rn(a1.z + b1.z, a1.w + b1.w);
    uint4 pack;
    pack.x = *reinterpret_cast<unsigned int*>(&h0);
    pack.y = *reinterpret_cast<unsigned int*>(&h1);
    pack.z = *reinterpret_cast<unsigned int*>(&h2);
    pack.w = *reinterpret_cast<unsigned int*>(&h3);
    reinterpret_cast<uint4*>(g_S)[i] = pack;
}

__device__ __forceinline__ void cp16(unsigned int dst, const void* src) {
    asm volatile("cp.async.cg.shared.global [%0], [%1], 16;\n"
                 :: "r"(dst), "l"(src) : "memory");
}
__device__ __forceinline__ void cp_commit() {
    asm volatile("cp.async.commit_group;\n" ::: "memory");
}
__device__ __forceinline__ void gbar(int id) {
    asm volatile("bar.sync %0, 128;" :: "r"(id) : "memory");
}
__device__ __forceinline__ __half2 u2h(unsigned int u) {
    return *reinterpret_cast<__half2*>(&u);
}

// ---- Kernel 2: R15 base; Phase E deferred into B2->B3 window (warps 1-3),
//      parallel with warp 0's softmax; 2 barriers per node ----
__global__ __launch_bounds__(512, 2)
void community_kernel(const float* __restrict__ Wscore,
                      const float* __restrict__ Wfit,
                      const float* __restrict__ bfit,
                      float* __restrict__ out_cluster,   // [NODE_NUM, C]
                      float* __restrict__ out_scores,    // [NODE_NUM, D]
                      float* __restrict__ out_fit,       // [NODE_NUM]
                      const int* __restrict__ neighbors)
{
    extern __shared__ char smem[];

    const int t    = threadIdx.x;
    const int lane = t & 31;
    const int wid  = t >> 5;     // 0..15
    const int g    = wid >> 2;   // group 0..3
    const int gw   = wid & 3;    // warp within group
    const int tg   = t & 127;    // thread within group
    const int barid = g + 1;

    char*  stg_b = smem + OFF_STAGE + g * 16384;                // group stage, bytes
    __half2* stg = (__half2*)stg_b;                             // [64][64] half2
    uint2* partA = (uint2*)(smem + OFF_PARTA) + g * 128;        // [4][32] fp16 colmax
    float* partP = (float*)(smem + OFF_PARTP) + g * 512;        // pool partials
    float* srawg = (float*)(smem + OFF_SRAW) + g * 64;
    float* sarrg = (float*)(smem + OFF_SARR) + g * 64;
    float* wredg = (float*)(smem + OFF_WRED) + g * 8;           // [2][4] parity
    const unsigned int stg_u = (unsigned int)__cvta_generic_to_shared(stg_b);
    const char* Sbase = (const char*)g_S;

    // loop-invariant weights (gv4 loaded via __ldg inside softmax: reg relief)
    const float4 w2v   = *reinterpret_cast<const float4*>(Wscore + C_DIM + 4 * lane);
    const float  wfitA = Wfit[tg];
    const float  wfitB = (gw == 1) ? Wfit[tg - 32] : 0.f;   // warp1 covers ch 0..31 too
    const float  bfitv = bfit[0];
    const float  c0    = g_c0;
    const __half2 NEGINF2 = __halves2half2(__ushort_as_half(0xFC00u),
                                           __ushort_as_half(0xFC00u));

    int node  = blockIdx.x * GROUPS + g;
    int eprev = -1;   // node with E (cluster/fitness-partial) pending
    int fprev = -1;   // node with fitness-final pending
    int par   = 0;

    // ---- prologue: stage first node's rows in TWO commit groups ----
    {
        int myid = 0;
        if (lane < 16) myid = neighbors[node * D_DEG + gw * 16 + lane];
#pragma unroll
        for (int i = 0; i < 4; i++) {         // chunks for rows 0..7 of block
            int c  = lane + 32 * i;
            int r  = c >> 4, ch = c & 15;
            long long nid = __shfl_sync(0xffffffffu, myid, r);
            int row = gw * 16 + r;
            cp16(stg_u + (unsigned)(row * 256 + ch * 16), Sbase + nid * 256 + ch * 16);
        }
        cp_commit();                           // G1: rows 0..7
#pragma unroll
        for (int i = 4; i < 8; i++) {         // chunks for rows 8..15
            int c  = lane + 32 * i;
            int r  = c >> 4, ch = c & 15;
            long long nid = __shfl_sync(0xffffffffu, myid, r);
            int row = gw * 16 + r;
            cp16(stg_u + (unsigned)(row * 256 + ch * 16), Sbase + nid * 256 + ch * 16);
        }
        cp_commit();                           // G2: rows 8..15
    }

    while (true) {
        const int  next     = node + GSTREAMS;
        const bool has_next = (next < NODE_NUM);

        // ---- next-node ids loaded at loop top (idle LSU slot) ----
        int myid2 = 0;
        if (has_next && lane < 16) myid2 = neighbors[next * D_DEG + gw * 16 + lane];

        asm volatile("cp.async.wait_group 1;\n" ::: "memory");   // G1: rows 0..7 ready

        // ---- Phase A: quad row-dot reduction + fp16 colmax; split halves ----
        __half2 cmx0 = NEGINF2, cmx1 = NEGINF2;
#pragma unroll
        for (int k = 0; k < 4; k++) {
            if (k == 2)
                asm volatile("cp.async.wait_group 0;\n" ::: "memory");  // G2: rows 8..15
            int r0 = gw * 16 + 4 * k;
            uint2 u0 = *reinterpret_cast<const uint2*>(stg + (r0 + 0) * 64 + lane * 2);
            uint2 u1 = *reinterpret_cast<const uint2*>(stg + (r0 + 1) * 64 + lane * 2);
            uint2 u2 = *reinterpret_cast<const uint2*>(stg + (r0 + 2) * 64 + lane * 2);
            uint2 u3 = *reinterpret_cast<const uint2*>(stg + (r0 + 3) * 64 + lane * 2);
            __half2 a0x = u2h(u0.x), a0y = u2h(u0.y);
            __half2 a1x = u2h(u1.x), a1y = u2h(u1.y);
            __half2 a2x = u2h(u2.x), a2y = u2h(u2.y);
            __half2 a3x = u2h(u3.x), a3y = u2h(u3.y);
            cmx0 = __hmax2(cmx0, __hmax2(__hmax2(a0x, a1x), __hmax2(a2x, a3x)));
            cmx1 = __hmax2(cmx1, __hmax2(__hmax2(a0y, a1y), __hmax2(a2y, a3y)));
            float2 f0x = __half22float2(a0x), f0y = __half22float2(a0y);
            float2 f1x = __half22float2(a1x), f1y = __half22float2(a1y);
            float2 f2x = __half22float2(a2x), f2y = __half22float2(a2y);
            float2 f3x = __half22float2(a3x), f3y = __half22float2(a3y);
            float p0 = f0x.x * w2v.x + f0x.y * w2v.y + f0y.x * w2v.z + f0y.y * w2v.w;
            float p1 = f1x.x * w2v.x + f1x.y * w2v.y + f1y.x * w2v.z + f1y.y * w2v.w;
            float p2 = f2x.x * w2v.x + f2x.y * w2v.y + f2y.x * w2v.z + f2y.y * w2v.w;
            float p3 = f3x.x * w2v.x + f3x.y * w2v.y + f3y.x * w2v.z + f3y.y * w2v.w;
            // quad butterfly: lane%4 == m ends with row r0+m's full dot
            float tA = (lane & 1) ? p0 : p1;
            tA = __shfl_xor_sync(0xffffffffu, tA, 1);
            float v01 = ((lane & 1) ? p1 : p0) + tA;
            float tB = (lane & 1) ? p2 : p3;
            tB = __shfl_xor_sync(0xffffffffu, tB, 1);
            float v23 = ((lane & 1) ? p3 : p2) + tB;
            float tC = (lane & 2) ? v01 : v23;
            tC = __shfl_xor_sync(0xffffffffu, tC, 2);
            float v = ((lane & 2) ? v23 : v01) + tC;
            v += __shfl_xor_sync(0xffffffffu, v, 4);
            v += __shfl_xor_sync(0xffffffffu, v, 8);
            v += __shfl_xor_sync(0xffffffffu, v, 16);
            if (lane < 4) srawg[r0 + lane] = v;
        }
        partA[gw * 32 + lane] = make_uint2(*reinterpret_cast<unsigned int*>(&cmx0),
                                           *reinterpret_cast<unsigned int*>(&cmx1));
        gbar(barid);   // B2: partA + sraw visible; orders prev partP + wred writes

        if (gw == 0) {
            // ---- deferred fitness-final for node two iterations back ----
            if (fprev >= 0 && lane == 0) {
                int q = (1 - par) * 4;
                float s = wredg[q + 1] + wredg[q + 2] + wredg[q + 3] + bfitv;
                out_fit[fprev] = 1.f / (1.f + __expf(-s));
            }
            // ---- colmax combine -> s_const -> softmax -> sarr ----
            uint2 m0 = partA[0   + lane], m1 = partA[32  + lane];
            uint2 m2 = partA[64  + lane], m3 = partA[96  + lane];
            __half2 x0 = __hmax2(__hmax2(u2h(m0.x), u2h(m1.x)),
                                 __hmax2(u2h(m2.x), u2h(m3.x)));
            __half2 x1 = __hmax2(__hmax2(u2h(m0.y), u2h(m1.y)),
                                 __hmax2(u2h(m2.y), u2h(m3.y)));
            float2 c01 = __half22float2(x0);
            float2 c23 = __half22float2(x1);
            const float4 gv4 = __ldg(reinterpret_cast<const float4*>(g_v + 4 * lane));
            float p = c01.x * gv4.x + c01.y * gv4.y + c23.x * gv4.z + c23.y * gv4.w;
#pragma unroll
            for (int o = 16; o > 0; o >>= 1) p += __shfl_xor_sync(0xffffffffu, p, o);
            const float s_const = p + c0;

            float a0 = s_const + srawg[lane];
            float a1 = s_const + srawg[lane + 32];
            a0 = (a0 >= 0.f) ? a0 : NEG_SLOPE * a0;
            a1 = (a1 >= 0.f) ? a1 : NEG_SLOPE * a1;
            float mx = fmaxf(a0, a1);
#pragma unroll
            for (int o = 16; o > 0; o >>= 1) mx = fmaxf(mx, __shfl_xor_sync(0xffffffffu, mx, o));
            float e0 = __expf(a0 - mx), e1 = __expf(a1 - mx);
            float sm = e0 + e1;
#pragma unroll
            for (int o = 16; o > 0; o >>= 1) sm += __shfl_xor_sync(0xffffffffu, sm, o);
            float inv = 1.f / sm;
            float s0 = e0 * inv, s1 = e1 * inv;
            sarrg[lane]      = s0;
            sarrg[lane + 32] = s1;
            out_scores[node * D_DEG + lane]      = s0;
            out_scores[node * D_DEG + lane + 32] = s1;
        } else if (eprev >= 0) {
            // ---- Phase E for previous node, hidden under warp 0's softmax ----
            float cf = partP[tg] + partP[128 + tg] + partP[256 + tg] + partP[384 + tg];
            out_cluster[(size_t)eprev * C_DIM + tg] = cf;
            float p = cf * wfitA;
            if (gw == 1) {
                int ch2 = tg - 32;   // warp1 also covers channels 0..31
                float cf2 = partP[ch2] + partP[128 + ch2] + partP[256 + ch2] + partP[384 + ch2];
                out_cluster[(size_t)eprev * C_DIM + ch2] = cf2;
                p += cf2 * wfitB;
            }
#pragma unroll
            for (int o = 16; o > 0; o >>= 1) p += __shfl_xor_sync(0xffffffffu, p, o);
            if (lane == 0) wredg[par * 4 + gw] = p;   // slots 1..3 at parity par
        }
        gbar(barid);   // B3: sarr ready (E writes ordered for next iter's readers)

        // ---- Phase D: weighted pooling; prefetch interleaved, 2 commit groups ----
        {
            float a0 = 0.f, a1 = 0.f, a2 = 0.f, a3 = 0.f;
#pragma unroll
            for (int r = 0; r < 16; r++) {
                int row = gw * 16 + r;
                float sc = sarrg[row];   // LDS broadcast
                uint2 u = *reinterpret_cast<const uint2*>(stg + row * 64 + lane * 2);
                float2 f0 = __half22float2(u2h(u.x));
                float2 f1 = __half22float2(u2h(u.y));
                a0 = fmaf(sc, f0.x, a0); a1 = fmaf(sc, f0.y, a1);
                a2 = fmaf(sc, f1.x, a2); a3 = fmaf(sc, f1.y, a3);
                // after the odd row of each pair is consumed, refill that pair
                if ((r & 1) && has_next) {
                    int pair = r >> 1;                  // 0..7
                    int c  = pair * 32 + lane;          // chunk id 0..255
                    int rr = c >> 4, ch = c & 15;       // rr in {2*pair, 2*pair+1} <= r
                    long long nid = __shfl_sync(0xffffffffu, myid2, rr);
                    int wrow = gw * 16 + rr;
                    cp16(stg_u + (unsigned)(wrow * 256 + ch * 16),
                         Sbase + nid * 256 + ch * 16);
                    if (r == 7)  cp_commit();           // G1: rows 0..7
                    if (r == 15) cp_commit();           // G2: rows 8..15
                }
            }
            *reinterpret_cast<float4*>(partP + gw * 128 + lane * 4) = make_float4(a0, a1, a2, a3);
        }
        // no barrier here: partP(node) consumed after next iteration's B2

        fprev = eprev;
        eprev = node;
        par ^= 1;
        if (!has_next) break;
        node = next;
    }

    // ---- tail: E(last node) + final two fitness values ----
    gbar(barid);   // orders partP(last D) + last in-loop wred writes
    if (gw != 0) {
        float cf = partP[tg] + partP[128 + tg] + partP[256 + tg] + partP[384 + tg];
        out_cluster[(size_t)eprev * C_DIM + tg] = cf;
        float p = cf * wfitA;
        if (gw == 1) {
            int ch2 = tg - 32;
            float cf2 = partP[ch2] + partP[128 + ch2] + partP[256 + ch2] + partP[384 + ch2];
            out_cluster[(size_t)eprev * C_DIM + ch2] = cf2;
            p += cf2 * wfitB;
        }
#pragma unroll
        for (int o = 16; o > 0; o >>= 1) p += __shfl_xor_sync(0xffffffffu, p, o);
        if (lane == 0) wredg[par * 4 + gw] = p;
    } else if (fprev >= 0 && lane == 0) {
        int q = (1 - par) * 4;
        float s = wredg[q + 1] + wredg[q + 2] + wredg[q + 3] + bfitv;
        out_fit[fprev] = 1.f / (1.f + __expf(-s));
    }
    gbar(barid);
    if (tg == 0) {
        int q = par * 4;
        float s = wredg[q + 1] + wredg[q + 2] + wredg[q + 3] + bfitv;
        out_fit[eprev] = 1.f / (1.f + __expf(-s));
    }
}

extern "C" void kernel_launch(void* const* d_in, const int* in_sizes, int n_in,
                              void* d_out, int out_size) {
    const float* feat   = (const float*)d_in[0];
    const float* mem    = (const float*)d_in[1];
    const float* Wmax   = (const float*)d_in[2];
    const float* bmax   = (const float*)d_in[3];
    const float* Wscore = (const float*)d_in[4];
    const float* bscore = (const float*)d_in[5];
    const float* Wfit   = (const float*)d_in[6];
    const float* bfit   = (const float*)d_in[7];
    const int*   nbrs   = (const int*)d_in[8];

    float* out = (float*)d_out;
    float* out_cluster = out;                                        // 8192*128
    float* out_scores  = out + NODE_NUM * C_DIM;                     // 8192*64
    float* out_fit     = out + NODE_NUM * C_DIM + NODE_NUM * D_DEG;  // 8192

    cudaFuncSetAttribute(community_kernel,
                         cudaFuncAttributeMaxDynamicSharedMemorySize, SMEM_BYTES);

    // 6250 x 512 threads == 3.2M == exactly one 16B S-store per thread
    fuse_kernel<<<6250, 512>>>((const float4*)feat, (const float4*)mem,
                               Wmax, bmax, Wscore, bscore);
    community_kernel<<<GRID_CTAS, 512, SMEM_BYTES>>>(Wscore, Wfit, bfit,
                                                     out_cluster, out_scores, out_fit, nbrs);
}

// round 17
// speedup vs baseline: 1.1690x; 1.0638x over previous
#include <cuda_runtime.h>
#include <cuda_fp16.h>
#include <math_constants.h>
#include <cstdint>

#define C_DIM 128
#define D_DEG 64
#define NODE_NUM 8192
#define N_TOTAL 200000
#define NEG_SLOPE 0.2f
#define GRID_CTAS 296        // 2 persistent CTAs per SM
#define GROUPS 4             // independent 128-thread groups per CTA
#define GSTREAMS (GRID_CTAS * GROUPS)   // 1184 node streams

// smem layout (dynamic)
#define OFF_STAGE 0                 // [4][64][128] fp16 = 64KB (warp-private rows)
#define OFF_PARTA 65536             // [4][4][32] uint2 fp16 colmax partials = 4KB
#define OFF_PARTP 69632             // [4][4][128] f32 pool partials = 8KB
#define OFF_SRAW  77824             // [4][64] f32 = 1KB
#define OFF_SARR  78848             // [4][64] f32 = 1KB
#define OFF_WRED  79872             // [4][2][4] f32 parity-buffered fitness partials
#define SMEM_BYTES 80000

// Fused fp16 table: S[n][c] = fp16(feat[n][c] + mem[n][c]); 51.2MB static scratch.
__device__ __half2 g_S[(size_t)N_TOTAL * (C_DIM / 2)];
// Per-node score dot: d[n] = dot(feat[n]+mem[n], W_score[128:256])  (fp32 exact)
__device__ float g_d[N_TOTAL];
// Folded weights: v = W_max @ W_score[:128]; c0 = dot(b_max, W_score[:128]) + b_score
__device__ float g_v[C_DIM];
__device__ float g_c0;

// ---- Kernel 1: streaming fuse + per-row score dot + weight folding ----
__global__ __launch_bounds__(512)
void fuse_kernel(const float4* __restrict__ feat4,
                 const float4* __restrict__ mem4,
                 const float* __restrict__ Wmax,
                 const float* __restrict__ bmax,
                 const float* __restrict__ Wscore,
                 const float* __restrict__ bscore) {
    if (blockIdx.x == 0) {
        __shared__ float ws1[C_DIM];
        int t = threadIdx.x;
        if (t < C_DIM) ws1[t] = Wscore[t];
        __syncthreads();
        if (t < C_DIM) {
            const float* row = Wmax + t * C_DIM;
            float acc = 0.f;
#pragma unroll 8
            for (int k = 0; k < C_DIM; k++) acc += row[k] * ws1[k];
            g_v[t] = acc;
            if (t == 0) {
                float c0 = bscore[0];
                for (int k = 0; k < C_DIM; k++) c0 += bmax[k] * ws1[k];
                g_c0 = c0;
            }
        }
    }
    // exactly one uint4 store per thread: grid 6250 x 512 == 3.2M
    const int i = blockIdx.x * blockDim.x + threadIdx.x;
    const int q = i & 15;            // 16B chunk within row -> channels 8q..8q+7
    // streaming (evict-first) reads keep the S output resident in L2
    float4 a0 = __ldcs(feat4 + 2 * i);
    float4 b0 = __ldcs(mem4 + 2 * i);
    float4 a1 = __ldcs(feat4 + 2 * i + 1);
    float4 b1 = __ldcs(mem4 + 2 * i + 1);
    float s0 = a0.x + b0.x, s1 = a0.y + b0.y, s2 = a0.z + b0.z, s3 = a0.w + b0.w;
    float s4 = a1.x + b1.x, s5 = a1.y + b1.y, s6 = a1.z + b1.z, s7 = a1.w + b1.w;

    // fp16 pack + store
    __half2 h0 = __floats2half2_rn(s0, s1);
    __half2 h1 = __floats2half2_rn(s2, s3);
    __half2 h2 = __floats2half2_rn(s4, s5);
    __half2 h3 = __floats2half2_rn(s6, s7);
    uint4 pack;
    pack.x = *reinterpret_cast<unsigned int*>(&h0);
    pack.y = *reinterpret_cast<unsigned int*>(&h1);
    pack.z = *reinterpret_cast<unsigned int*>(&h2);
    pack.w = *reinterpret_cast<unsigned int*>(&h3);
    reinterpret_cast<uint4*>(g_S)[i] = pack;

    // fp32 partial dot with W_score[128+8q .. 128+8q+7], reduced over the
    // 16 threads of each row (half-warp segmented butterfly)
    const float4 wA = *reinterpret_cast<const float4*>(Wscore + C_DIM + 8 * q);
    const float4 wB = *reinterpret_cast<const float4*>(Wscore + C_DIM + 8 * q + 4);
    float p = s0 * wA.x + s1 * wA.y + s2 * wA.z + s3 * wA.w
            + s4 * wB.x + s5 * wB.y + s6 * wB.z + s7 * wB.w;
    p += __shfl_xor_sync(0xffffffffu, p, 1);
    p += __shfl_xor_sync(0xffffffffu, p, 2);
    p += __shfl_xor_sync(0xffffffffu, p, 4);
    p += __shfl_xor_sync(0xffffffffu, p, 8);
    if (q == 0) g_d[i >> 4] = p;
}

__device__ __forceinline__ void cp16(unsigned int dst, const void* src) {
    asm volatile("cp.async.cg.shared.global [%0], [%1], 16;\n"
                 :: "r"(dst), "l"(src) : "memory");
}
__device__ __forceinline__ void cp_commit() {
    asm volatile("cp.async.commit_group;\n" ::: "memory");
}
__device__ __forceinline__ void gbar(int id) {
    asm volatile("bar.sync %0, 128;" :: "r"(id) : "memory");
}
__device__ __forceinline__ __half2 u2h(unsigned int u) {
    return *reinterpret_cast<__half2*>(&u);
}

// ---- Kernel 2: R16 base; Phase A reduced to colmax-only (dot precomputed) ----
__global__ __launch_bounds__(512, 2)
void community_kernel(const float* __restrict__ Wfit,
                      const float* __restrict__ bfit,
                      float* __restrict__ out_cluster,   // [NODE_NUM, C]
                      float* __restrict__ out_scores,    // [NODE_NUM, D]
                      float* __restrict__ out_fit,       // [NODE_NUM]
                      const int* __restrict__ neighbors)
{
    extern __shared__ char smem[];

    const int t    = threadIdx.x;
    const int lane = t & 31;
    const int wid  = t >> 5;     // 0..15
    const int g    = wid >> 2;   // group 0..3
    const int gw   = wid & 3;    // warp within group
    const int tg   = t & 127;    // thread within group
    const int barid = g + 1;

    char*  stg_b = smem + OFF_STAGE + g * 16384;                // group stage, bytes
    __half2* stg = (__half2*)stg_b;                             // [64][64] half2
    uint2* partA = (uint2*)(smem + OFF_PARTA) + g * 128;        // [4][32] fp16 colmax
    float* partP = (float*)(smem + OFF_PARTP) + g * 512;        // pool partials
    float* srawg = (float*)(smem + OFF_SRAW) + g * 64;
    float* sarrg = (float*)(smem + OFF_SARR) + g * 64;
    float* wredg = (float*)(smem + OFF_WRED) + g * 8;           // [2][4] parity
    const unsigned int stg_u = (unsigned int)__cvta_generic_to_shared(stg_b);
    const char* Sbase = (const char*)g_S;

    // loop-invariant weights
    const float  wfitA = Wfit[tg];
    const float  wfitB = (gw == 1) ? Wfit[tg - 32] : 0.f;   // warp1 covers ch 0..31 too
    const float  bfitv = bfit[0];
    const float  c0    = g_c0;
    const __half2 NEGINF2 = __halves2half2(__ushort_as_half(0xFC00u),
                                           __ushort_as_half(0xFC00u));

    int node  = blockIdx.x * GROUPS + g;
    int eprev = -1;   // node with E (cluster/fitness-partial) pending
    int fprev = -1;   // node with fitness-final pending
    int par   = 0;

    // ---- current node ids (persist across the iteration) ----
    int myid = 0;
    if (lane < 16) myid = neighbors[node * D_DEG + gw * 16 + lane];

    // ---- prologue: stage first node's rows in TWO commit groups ----
    {
#pragma unroll
        for (int i = 0; i < 4; i++) {         // chunks for rows 0..7 of block
            int c  = lane + 32 * i;
            int r  = c >> 4, ch = c & 15;
            long long nid = __shfl_sync(0xffffffffu, myid, r);
            int row = gw * 16 + r;
            cp16(stg_u + (unsigned)(row * 256 + ch * 16), Sbase + nid * 256 + ch * 16);
        }
        cp_commit();                           // G1: rows 0..7
#pragma unroll
        for (int i = 4; i < 8; i++) {         // chunks for rows 8..15
            int c  = lane + 32 * i;
            int r  = c >> 4, ch = c & 15;
            long long nid = __shfl_sync(0xffffffffu, myid, r);
            int row = gw * 16 + r;
            cp16(stg_u + (unsigned)(row * 256 + ch * 16), Sbase + nid * 256 + ch * 16);
        }
        cp_commit();                           // G2: rows 8..15
    }

    while (true) {
        const int  next     = node + GSTREAMS;
        const bool has_next = (next < NODE_NUM);

        // ---- loop top: next-node ids + this node's precomputed dots ----
        int myid2 = 0;
        if (has_next && lane < 16) myid2 = neighbors[next * D_DEG + gw * 16 + lane];
        float dval = 0.f;
        if (lane < 16) dval = __ldg(g_d + myid);

        asm volatile("cp.async.wait_group 1;\n" ::: "memory");   // G1: rows 0..7 ready

        // ---- Phase A: fp16 colmax only over own 16 rows (dot precomputed) ----
        __half2 cmx0 = NEGINF2, cmx1 = NEGINF2;
#pragma unroll
        for (int k = 0; k < 4; k++) {
            if (k == 2)
                asm volatile("cp.async.wait_group 0;\n" ::: "memory");  // G2: rows 8..15
            int r0 = gw * 16 + 4 * k;
            uint2 u0 = *reinterpret_cast<const uint2*>(stg + (r0 + 0) * 64 + lane * 2);
            uint2 u1 = *reinterpret_cast<const uint2*>(stg + (r0 + 1) * 64 + lane * 2);
            uint2 u2 = *reinterpret_cast<const uint2*>(stg + (r0 + 2) * 64 + lane * 2);
            uint2 u3 = *reinterpret_cast<const uint2*>(stg + (r0 + 3) * 64 + lane * 2);
            cmx0 = __hmax2(cmx0, __hmax2(__hmax2(u2h(u0.x), u2h(u1.x)),
                                         __hmax2(u2h(u2.x), u2h(u3.x))));
            cmx1 = __hmax2(cmx1, __hmax2(__hmax2(u2h(u0.y), u2h(u1.y)),
                                         __hmax2(u2h(u2.y), u2h(u3.y))));
        }
        partA[gw * 32 + lane] = make_uint2(*reinterpret_cast<unsigned int*>(&cmx0),
                                           *reinterpret_cast<unsigned int*>(&cmx1));
        if (lane < 16) srawg[gw * 16 + lane] = dval;
        gbar(barid);   // B2: partA + sraw visible; orders prev partP + wred writes

        if (gw == 0) {
            // ---- deferred fitness-final for node two iterations back ----
            if (fprev >= 0 && lane == 0) {
                int q = (1 - par) * 4;
                float s = wredg[q + 1] + wredg[q + 2] + wredg[q + 3] + bfitv;
                out_fit[fprev] = 1.f / (1.f + __expf(-s));
            }
            // ---- colmax combine -> s_const -> softmax -> sarr ----
            uint2 m0 = partA[0   + lane], m1 = partA[32  + lane];
            uint2 m2 = partA[64  + lane], m3 = partA[96  + lane];
            __half2 x0 = __hmax2(__hmax2(u2h(m0.x), u2h(m1.x)),
                                 __hmax2(u2h(m2.x), u2h(m3.x)));
            __half2 x1 = __hmax2(__hmax2(u2h(m0.y), u2h(m1.y)),
                                 __hmax2(u2h(m2.y), u2h(m3.y)));
            float2 c01 = __half22float2(x0);
            float2 c23 = __half22float2(x1);
            const float4 gv4 = __ldg(reinterpret_cast<const float4*>(g_v + 4 * lane));
            float p = c01.x * gv4.x + c01.y * gv4.y + c23.x * gv4.z + c23.y * gv4.w;
#pragma unroll
            for (int o = 16; o > 0; o >>= 1) p += __shfl_xor_sync(0xffffffffu, p, o);
            const float s_const = p + c0;

            float a0 = s_const + srawg[lane];
            float a1 = s_const + srawg[lane + 32];
            a0 = (a0 >= 0.f) ? a0 : NEG_SLOPE * a0;
            a1 = (a1 >= 0.f) ? a1 : NEG_SLOPE * a1;
            float mx = fmaxf(a0, a1);
#pragma unroll
            for (int o = 16; o > 0; o >>= 1) mx = fmaxf(mx, __shfl_xor_sync(0xffffffffu, mx, o));
            float e0 = __expf(a0 - mx), e1 = __expf(a1 - mx);
            float sm = e0 + e1;
#pragma unroll
            for (int o = 16; o > 0; o >>= 1) sm += __shfl_xor_sync(0xffffffffu, sm, o);
            float inv = 1.f / sm;
            float s0 = e0 * inv, s1 = e1 * inv;
            sarrg[lane]      = s0;
            sarrg[lane + 32] = s1;
            out_scores[node * D_DEG + lane]      = s0;
            out_scores[node * D_DEG + lane + 32] = s1;
        } else if (eprev >= 0) {
            // ---- Phase E for previous node, hidden under warp 0's softmax ----
            float cf = partP[tg] + partP[128 + tg] + partP[256 + tg] + partP[384 + tg];
            out_cluster[(size_t)eprev * C_DIM + tg] = cf;
            float p = cf * wfitA;
            if (gw == 1) {
                int ch2 = tg - 32;   // warp1 also covers channels 0..31
                float cf2 = partP[ch2] + partP[128 + ch2] + partP[256 + ch2] + partP[384 + ch2];
                out_cluster[(size_t)eprev * C_DIM + ch2] = cf2;
                p += cf2 * wfitB;
            }
#pragma unroll
            for (int o = 16; o > 0; o >>= 1) p += __shfl_xor_sync(0xffffffffu, p, o);
            if (lane == 0) wredg[par * 4 + gw] = p;   // slots 1..3 at parity par
        }
        gbar(barid);   // B3: sarr ready (E writes ordered for next iter's readers)

        // ---- Phase D: weighted pooling; prefetch interleaved, 2 commit groups ----
        {
            float a0 = 0.f, a1 = 0.f, a2 = 0.f, a3 = 0.f;
#pragma unroll
            for (int r = 0; r < 16; r++) {
                int row = gw * 16 + r;
                float sc = sarrg[row];   // LDS broadcast
                uint2 u = *reinterpret_cast<const uint2*>(stg + row * 64 + lane * 2);
                float2 f0 = __half22float2(u2h(u.x));
                float2 f1 = __half22float2(u2h(u.y));
                a0 = fmaf(sc, f0.x, a0); a1 = fmaf(sc, f0.y, a1);
                a2 = fmaf(sc, f1.x, a2); a3 = fmaf(sc, f1.y, a3);
                // after the odd row of each pair is consumed, refill that pair
                if ((r & 1) && has_next) {
                    int pair = r >> 1;                  // 0..7
                    int c  = pair * 32 + lane;          // chunk id 0..255
                    int rr = c >> 4, ch = c & 15;       // rr in {2*pair, 2*pair+1} <= r
                    long long nid = __shfl_sync(0xffffffffu, myid2, rr);
                    int wrow = gw * 16 + rr;
                    cp16(stg_u + (unsigned)(wrow * 256 + ch * 16),
                         Sbase + nid * 256 + ch * 16);
                    if (r == 7)  cp_commit();           // G1: rows 0..7
                    if (r == 15) cp_commit();           // G2: rows 8..15
                }
            }
            *reinterpret_cast<float4*>(partP + gw * 128 + lane * 4) = make_float4(a0, a1, a2, a3);
        }
        // no barrier here: partP(node) consumed after next iteration's B2

        fprev = eprev;
        eprev = node;
        par ^= 1;
        myid = myid2;
        if (!has_next) break;
        node = next;
    }

    // ---- tail: E(last node) + final two fitness values ----
    gbar(barid);   // orders partP(last D) + last in-loop wred writes
    if (gw != 0) {
        float cf = partP[tg] + partP[128 + tg] + partP[256 + tg] + partP[384 + tg];
        out_cluster[(size_t)eprev * C_DIM + tg] = cf;
        float p = cf * wfitA;
        if (gw == 1) {
            int ch2 = tg - 32;
            float cf2 = partP[ch2] + partP[128 + ch2] + partP[256 + ch2] + partP[384 + ch2];
            out_cluster[(size_t)eprev * C_DIM + ch2] = cf2;
            p += cf2 * wfitB;
        }
#pragma unroll
        for (int o = 16; o > 0; o >>= 1) p += __shfl_xor_sync(0xffffffffu, p, o);
        if (lane == 0) wredg[par * 4 + gw] = p;
    } else if (fprev >= 0 && lane == 0) {
        int q = (1 - par) * 4;
        float s = wredg[q + 1] + wredg[q + 2] + wredg[q + 3] + bfitv;
        out_fit[fprev] = 1.f / (1.f + __expf(-s));
    }
    gbar(barid);
    if (tg == 0) {
        int q = par * 4;
        float s = wredg[q + 1] + wredg[q + 2] + wredg[q + 3] + bfitv;
        out_fit[eprev] = 1.f / (1.f + __expf(-s));
    }
}

extern "C" void kernel_launch(void* const* d_in, const int* in_sizes, int n_in,
                              void* d_out, int out_size) {
    const float* feat   = (const float*)d_in[0];
    const float* mem    = (const float*)d_in[1];
    const float* Wmax   = (const float*)d_in[2];
    const float* bmax   = (const float*)d_in[3];
    const float* Wscore = (const float*)d_in[4];
    const float* bscore = (const float*)d_in[5];
    const float* Wfit   = (const float*)d_in[6];
    const float* bfit   = (const float*)d_in[7];
    const int*   nbrs   = (const int*)d_in[8];

    float* out = (float*)d_out;
    float* out_cluster = out;                                        // 8192*128
    float* out_scores  = out + NODE_NUM * C_DIM;                     // 8192*64
    float* out_fit     = out + NODE_NUM * C_DIM + NODE_NUM * D_DEG;  // 8192

    cudaFuncSetAttribute(community_kernel,
                         cudaFuncAttributeMaxDynamicSharedMemorySize, SMEM_BYTES);

    // 6250 x 512 threads == 3.2M == exactly one 16B S-store per thread
    fuse_kernel<<<6250, 512>>>((const float4*)feat, (const float4*)mem,
                               Wmax, bmax, Wscore, bscore);
    community_kernel<<<GRID_CTAS, 512, SMEM_BYTES>>>(Wfit, bfit,
                                                     out_cluster, out_scores, out_fit, nbrs);
}